// round 6
// baseline (speedup 1.0000x reference)
#include <cuda_runtime.h>
#include <cuda_bf16.h>
#include <cstdint>

// Problem constants
#define NROWS 32768
#define DIMK  512
#define NCB   16
#define CS    256

// Encoder tiling
#define TM    128
#define TN    256
#define KC    32
#define NCHUNK (DIMK / KC)   // 16
#define TPB   512

#define RECHECK_CAP 131072
#define RECHECK_BLOCKS 16384
#define GAP_TAU 0.03f

__device__ int g_idx[NROWS * NCB];
__device__ int g_cnt;
__device__ int g_list[RECHECK_CAP];

// ---------------- smem layout (dynamic) ----------------
#define SM_BIAS 0          // 256 f32 = 1024B
#define SM_V1   1024       // 128*4 f32 = 2048B
#define SM_V2   3072       // 2048B
#define SM_I1   5120       // 2048B (int)
#define SM_BUF  7168       // 2 x 30720
#define ASTR    80         // bytes per k-row (32 bf16 = 64B + 16B pad)
#define OFF_AH  0
#define OFF_BH  10240      // 128*80
#define BUFSZ   30720      // + 256*80
#define SMEM_TOTAL (SM_BUF + 2 * BUFSZ)   // 68608 B

__device__ __forceinline__ uint32_t smem_u32(const void* p) {
    uint32_t a;
    asm("{ .reg .u64 t; cvta.to.shared.u64 t, %1; cvt.u32.u64 %0, t; }"
        : "=r"(a) : "l"(p));
    return a;
}
__device__ __forceinline__ void ldm4(uint32_t r[4], uint32_t addr) {
    asm volatile("ldmatrix.sync.aligned.m8n8.x4.shared.b16 {%0,%1,%2,%3}, [%4];"
        : "=r"(r[0]), "=r"(r[1]), "=r"(r[2]), "=r"(r[3]) : "r"(addr));
}
__device__ __forceinline__ void mma_bf16(float d[4], const uint32_t a[4],
                                         uint32_t b0, uint32_t b1) {
    asm volatile("mma.sync.aligned.m16n8k16.row.col.f32.bf16.bf16.f32 "
        "{%0,%1,%2,%3},{%4,%5,%6,%7},{%8,%9},{%0,%1,%2,%3};"
        : "+f"(d[0]), "+f"(d[1]), "+f"(d[2]), "+f"(d[3])
        : "r"(a[0]), "r"(a[1]), "r"(a[2]), "r"(a[3]), "r"(b0), "r"(b1));
}
__device__ __forceinline__ uint32_t cvt2(float a, float b) {
    uint32_t r;
    asm("cvt.rn.bf16x2.f32 %0, %1, %2;" : "=r"(r) : "f"(b), "f"(a));
    return r;
}

// ---------------------------------------------------------------------------
// Kernel 1: pure-bf16 GEMM (mma.sync) + argmax + near-tie list.
// grid = (NCB, NROWS/TM)  [cb fastest -> x row tiles shared in L2 per wave]
// block = 512 (16 warps, 4m x 4n, warp tile 32x64).
// ---------------------------------------------------------------------------
__global__ __launch_bounds__(TPB, 1)
void enc_mma_kernel(const float* __restrict__ x,
                    const float* __restrict__ W,
                    const float* __restrict__ bias,
                    int* __restrict__ gidx)
{
    extern __shared__ char smem[];
    const uint32_t sb = smem_u32(smem);
    const int tid  = threadIdx.x;
    const int lane = tid & 31;
    const int wid  = tid >> 5;
    const int wm   = wid >> 2;    // 0..3
    const int wn   = wid & 3;     // 0..3
    const int cb   = blockIdx.x;
    const int row0 = blockIdx.y * TM;

    if (tid < CS)
        *reinterpret_cast<float*>(smem + SM_BIAS + tid * 4) = bias[cb * CS + tid];

    const float* xg = x + (size_t)row0 * DIMK;
    const float* Wg = W + (size_t)cb * CS * DIMK;

    float acc[2][8][4];
    #pragma unroll
    for (int i = 0; i < 2; ++i)
        #pragma unroll
        for (int j = 0; j < 8; ++j)
            #pragma unroll
            for (int k = 0; k < 4; ++k) acc[i][j][k] = 0.f;

    // per-lane ldmatrix address offsets (bytes, within a buffer)
    const uint32_t a_off = (uint32_t)((wm * 32 + (lane & 15)) * ASTR + ((lane >> 4) * 16));
    const uint32_t b_off = (uint32_t)((wn * 64 + (lane & 7) + ((lane & 16) >> 1)) * ASTR
                                      + (((lane >> 3) & 1) * 16));

    // ---- staging indices ----
    const int ar = tid >> 2, asg = tid & 3;        // A: row, 8-float segment
    const int bc = tid >> 1, bsg = tid & 1;        // B: col, 16-float segment

    #define STAGE(k0, bufp) do {                                                   \
        { /* A tile: 128x32 fp32 -> bf16 */                                        \
            const float4* s = reinterpret_cast<const float4*>(                     \
                xg + (size_t)ar * DIMK + (k0) + asg * 8);                           \
            float4 f0 = s[0], f1 = s[1];                                           \
            *reinterpret_cast<uint4*>((bufp) + OFF_AH + ar * ASTR + asg * 16) =     \
                make_uint4(cvt2(f0.x, f0.y), cvt2(f0.z, f0.w),                      \
                           cvt2(f1.x, f1.y), cvt2(f1.z, f1.w));                     \
        }                                                                          \
        { /* B tile: 256x32 fp32 -> bf16 */                                        \
            const float4* s = reinterpret_cast<const float4*>(                     \
                Wg + (size_t)bc * DIMK + (k0) + bsg * 16);                          \
            float4 f0 = s[0], f1 = s[1], f2 = s[2], f3 = s[3];                      \
            char* bp = (bufp) + OFF_BH + bc * ASTR + bsg * 32;                      \
            *reinterpret_cast<uint4*>(bp) =                                         \
                make_uint4(cvt2(f0.x, f0.y), cvt2(f0.z, f0.w),                      \
                           cvt2(f1.x, f1.y), cvt2(f1.z, f1.w));                     \
            *reinterpret_cast<uint4*>(bp + 16) =                                    \
                make_uint4(cvt2(f2.x, f2.y), cvt2(f2.z, f2.w),                      \
                           cvt2(f3.x, f3.y), cvt2(f3.z, f3.w));                     \
        }                                                                          \
    } while (0)

    STAGE(0, smem + SM_BUF);
    __syncthreads();

    #pragma unroll 1
    for (int c = 0; c < NCHUNK; ++c) {
        if (c + 1 < NCHUNK)
            STAGE((c + 1) * KC, smem + SM_BUF + ((c + 1) & 1) * BUFSZ);

        const uint32_t bbase = sb + SM_BUF + (c & 1) * BUFSZ;
        #pragma unroll
        for (int ks = 0; ks < 2; ++ks) {
            uint32_t ah[2][4];
            #pragma unroll
            for (int mi = 0; mi < 2; ++mi)
                ldm4(ah[mi], bbase + OFF_AH + a_off + mi * (16 * ASTR) + ks * 32);
            #pragma unroll
            for (int nh = 0; nh < 2; ++nh) {
                uint32_t bh[2][4];
                #pragma unroll
                for (int ng = 0; ng < 2; ++ng)
                    ldm4(bh[ng], bbase + OFF_BH + b_off
                         + (uint32_t)((nh * 32 + ng * 16) * ASTR) + ks * 32);
                #pragma unroll
                for (int mi = 0; mi < 2; ++mi) {
                    #pragma unroll
                    for (int nt = 0; nt < 4; ++nt) {
                        const int ng = nt >> 1, rr = (nt & 1) * 2;
                        mma_bf16(acc[mi][nh * 4 + nt], ah[mi],
                                 bh[ng][rr], bh[ng][rr + 1]);
                    }
                }
            }
        }
        __syncthreads();
    }
    #undef STAGE

    // ---- epilogue: bias + per-warp top-2 over warp's 64 cols ----
    const float* sbias = reinterpret_cast<const float*>(smem + SM_BIAS);
    float* sV1 = reinterpret_cast<float*>(smem + SM_V1);
    float* sV2 = reinterpret_cast<float*>(smem + SM_V2);
    int*   sI1 = reinterpret_cast<int*>(smem + SM_I1);

    const int g = lane >> 2, q = lane & 3;
    const int colbase = wn * 64;

    #pragma unroll
    for (int mi = 0; mi < 2; ++mi) {
        #pragma unroll
        for (int h8 = 0; h8 < 2; ++h8) {
            const int row_local = wm * 32 + mi * 16 + h8 * 8 + g;
            float bv = -3.402823466e38f, bv2 = -3.402823466e38f;
            int bc_ = 0;
            #pragma unroll
            for (int nt = 0; nt < 8; ++nt) {
                const int c0 = colbase + nt * 8 + 2 * q;
                float v0 = acc[mi][nt][h8 * 2 + 0] + sbias[c0];
                float v1 = acc[mi][nt][h8 * 2 + 1] + sbias[c0 + 1];
                if (v0 > bv) { bv2 = bv; bv = v0; bc_ = c0; }
                else if (v0 > bv2) bv2 = v0;
                if (v1 > bv) { bv2 = bv; bv = v1; bc_ = c0 + 1; }
                else if (v1 > bv2) bv2 = v1;
            }
            // merge across the 4 lanes sharing this row (q = 0..3)
            #pragma unroll
            for (int off = 1; off <= 2; off <<= 1) {
                float ov  = __shfl_xor_sync(0xffffffffu, bv,  off);
                float ov2 = __shfl_xor_sync(0xffffffffu, bv2, off);
                int   oc  = __shfl_xor_sync(0xffffffffu, bc_, off);
                if (ov > bv || (ov == bv && oc < bc_)) {
                    bv2 = fmaxf(bv, ov2); bv = ov; bc_ = oc;
                } else {
                    bv2 = fmaxf(bv2, ov);
                }
            }
            if (q == 0) {
                sV1[row_local * 4 + wn] = bv;
                sV2[row_local * 4 + wn] = bv2;
                sI1[row_local * 4 + wn] = bc_;
            }
        }
    }
    __syncthreads();

    // ---- final cross-warp merge: one thread per row ----
    if (tid < TM) {
        float bv = sV1[tid * 4], bv2 = sV2[tid * 4];
        int bc_ = sI1[tid * 4];
        #pragma unroll
        for (int w = 1; w < 4; ++w) {
            float ov = sV1[tid * 4 + w], ov2 = sV2[tid * 4 + w];
            int oc = sI1[tid * 4 + w];
            if (ov > bv) { bv2 = fmaxf(bv, ov2); bv = ov; bc_ = oc; }
            else bv2 = fmaxf(bv2, ov);
        }
        const int grow = row0 + tid;
        gidx[grow * NCB + cb] = bc_;
        if (bv - bv2 < GAP_TAU) {
            int pos = atomicAdd(&g_cnt, 1);
            if (pos < RECHECK_CAP) g_list[pos] = grow * NCB + cb;
        }
    }
}

// ---------------------------------------------------------------------------
__global__ void init_kernel() { g_cnt = 0; }

// ---------------------------------------------------------------------------
// Kernel 2: exact fp32 recheck of near-tie (row, cb) pairs (grid-strided).
// CRITICAL: per-column accumulation is a single sequential fma chain over
// k = 0..511 (bitwise identical to the round-1 kernel that matched the
// reference argmax on every pair). Do NOT split into partial sums.
// ---------------------------------------------------------------------------
__global__ __launch_bounds__(256)
void recheck_kernel(const float* __restrict__ x,
                    const float* __restrict__ W,
                    const float* __restrict__ bias,
                    int* __restrict__ gidx)
{
    int n = g_cnt;
    if (n > RECHECK_CAP) n = RECHECK_CAP;

    for (int item = blockIdx.x; item < n; item += gridDim.x) {
        const int enc = g_list[item];
        const int row = enc >> 4;
        const int cb  = enc & 15;
        const int tid = threadIdx.x;
        const int col = tid;

        const float* xr = x + (size_t)row * DIMK;
        const float* wr = W + (size_t)(cb * CS + col) * DIMK;
        float acc = 0.f;
        #pragma unroll 8
        for (int k = 0; k < DIMK; ++k)
            acc = fmaf(xr[k], wr[k], acc);
        float v = acc + bias[cb * CS + col];
        int c = col;

        #pragma unroll
        for (int off = 16; off; off >>= 1) {
            float ov = __shfl_xor_sync(0xffffffffu, v, off);
            int   oc = __shfl_xor_sync(0xffffffffu, c, off);
            if (ov > v || (ov == v && oc < c)) { v = ov; c = oc; }
        }
        __shared__ float rv[8];
        __shared__ int   rc[8];
        if ((tid & 31) == 0) { rv[tid >> 5] = v; rc[tid >> 5] = c; }
        __syncthreads();
        if (tid == 0) {
            #pragma unroll
            for (int w = 1; w < 8; ++w)
                if (rv[w] > v || (rv[w] == v && rc[w] < c)) { v = rv[w]; c = rc[w]; }
            gidx[row * NCB + cb] = c;
        }
        __syncthreads();
    }
}

// ---------------------------------------------------------------------------
// Kernel 3: decode — gather 16 centers per row, sum, scale.
// ---------------------------------------------------------------------------
__global__ __launch_bounds__(128)
void dec_gather_kernel(const float* __restrict__ centers,
                       const int* __restrict__ gidx,
                       const float* __restrict__ centers_scale,
                       float* __restrict__ out)
{
    __shared__ int   sidx[NCB];
    __shared__ float sscale;
    const int row = blockIdx.x;
    const int tid = threadIdx.x;

    if (tid < NCB) sidx[tid] = gidx[row * NCB + tid];
    if (tid == 0)  sscale = expf(10.0f * centers_scale[0]);
    __syncthreads();

    float4 s = make_float4(0.f, 0.f, 0.f, 0.f);
    #pragma unroll
    for (int c = 0; c < NCB; ++c) {
        const float4* p = reinterpret_cast<const float4*>(
            centers + ((size_t)((c << 8) + sidx[c])) * DIMK);
        float4 v = __ldg(&p[tid]);
        s.x += v.x; s.y += v.y; s.z += v.z; s.w += v.w;
    }
    float sc = sscale;
    s.x *= sc; s.y *= sc; s.z *= sc; s.w *= sc;
    reinterpret_cast<float4*>(out)[(size_t)row * (DIMK / 4) + tid] = s;
}

// ---------------------------------------------------------------------------
extern "C" void kernel_launch(void* const* d_in, const int* in_sizes, int n_in,
                              void* d_out, int out_size)
{
    const float* x       = (const float*)d_in[0];
    const float* W       = (const float*)d_in[1];
    const float* b       = (const float*)d_in[2];
    const float* centers = (const float*)d_in[3];
    const float* cscale  = (const float*)d_in[5];
    float* out           = (float*)d_out;

    int* gidx_ptr = nullptr;
    cudaGetSymbolAddress((void**)&gidx_ptr, g_idx);

    cudaFuncSetAttribute(enc_mma_kernel,
                         cudaFuncAttributeMaxDynamicSharedMemorySize, SMEM_TOTAL);

    init_kernel<<<1, 1>>>();
    dim3 grid1(NCB, NROWS / TM);   // cb fastest: row-tile x reused in L2 per wave
    enc_mma_kernel<<<grid1, TPB, SMEM_TOTAL>>>(x, W, b, gidx_ptr);
    recheck_kernel<<<RECHECK_BLOCKS, 256>>>(x, W, b, gidx_ptr);
    dec_gather_kernel<<<NROWS, 128>>>(centers, gidx_ptr, cscale, out);
}

// round 7
// speedup vs baseline: 13.4309x; 13.4309x over previous
#include <cuda_runtime.h>
#include <cuda_bf16.h>
#include <cstdint>

// Problem constants
#define NROWS 32768
#define DIMK  512
#define NCB   16
#define CS    256

// Encoder tiling
#define TM    128
#define TN    256
#define KC    32
#define NCHUNK (DIMK / KC)   // 16
#define TPB   512

#define GAP_TAU 0.03f
#define CAP_CB  32768            // max rows per cb (cannot overflow)

__device__ int g_idx[NROWS * NCB];
__device__ int g_cnt_cb[NCB];
__device__ int g_list_cb[NCB * CAP_CB];

// ---------------- enc smem layout (dynamic) ----------------
#define SM_BIAS 0          // 256 f32 = 1024B
#define SM_V1   1024       // 128*4 f32 = 2048B
#define SM_V2   3072       // 2048B
#define SM_I1   5120       // 2048B (int)
#define SM_BUF  7168       // 2 x 30720
#define ASTR    80         // bytes per k-row (32 bf16 = 64B + 16B pad)
#define OFF_AH  0
#define OFF_BH  10240      // 128*80
#define BUFSZ   30720      // + 256*80
#define SMEM_TOTAL (SM_BUF + 2 * BUFSZ)   // 68608 B

__device__ __forceinline__ uint32_t smem_u32(const void* p) {
    uint32_t a;
    asm("{ .reg .u64 t; cvta.to.shared.u64 t, %1; cvt.u32.u64 %0, t; }"
        : "=r"(a) : "l"(p));
    return a;
}
__device__ __forceinline__ void ldm4(uint32_t r[4], uint32_t addr) {
    asm volatile("ldmatrix.sync.aligned.m8n8.x4.shared.b16 {%0,%1,%2,%3}, [%4];"
        : "=r"(r[0]), "=r"(r[1]), "=r"(r[2]), "=r"(r[3]) : "r"(addr));
}
__device__ __forceinline__ void mma_bf16(float d[4], const uint32_t a[4],
                                         uint32_t b0, uint32_t b1) {
    asm volatile("mma.sync.aligned.m16n8k16.row.col.f32.bf16.bf16.f32 "
        "{%0,%1,%2,%3},{%4,%5,%6,%7},{%8,%9},{%0,%1,%2,%3};"
        : "+f"(d[0]), "+f"(d[1]), "+f"(d[2]), "+f"(d[3])
        : "r"(a[0]), "r"(a[1]), "r"(a[2]), "r"(a[3]), "r"(b0), "r"(b1));
}
__device__ __forceinline__ uint32_t cvt2(float a, float b) {
    uint32_t r;
    asm("cvt.rn.bf16x2.f32 %0, %1, %2;" : "=r"(r) : "f"(b), "f"(a));
    return r;
}

// ---------------------------------------------------------------------------
// Kernel 1: pure-bf16 GEMM (mma.sync) + argmax + near-tie list (per-cb).
// grid = (NCB, NROWS/TM), block = 512 (16 warps, 4m x 4n, warp tile 32x64).
// ---------------------------------------------------------------------------
__global__ __launch_bounds__(TPB, 1)
void enc_mma_kernel(const float* __restrict__ x,
                    const float* __restrict__ W,
                    const float* __restrict__ bias,
                    int* __restrict__ gidx)
{
    extern __shared__ char smem[];
    const uint32_t sb = smem_u32(smem);
    const int tid  = threadIdx.x;
    const int lane = tid & 31;
    const int wid  = tid >> 5;
    const int wm   = wid >> 2;    // 0..3
    const int wn   = wid & 3;     // 0..3
    const int cb   = blockIdx.x;
    const int row0 = blockIdx.y * TM;

    if (tid < CS)
        *reinterpret_cast<float*>(smem + SM_BIAS + tid * 4) = bias[cb * CS + tid];

    const float* xg = x + (size_t)row0 * DIMK;
    const float* Wg = W + (size_t)cb * CS * DIMK;

    float acc[2][8][4];
    #pragma unroll
    for (int i = 0; i < 2; ++i)
        #pragma unroll
        for (int j = 0; j < 8; ++j)
            #pragma unroll
            for (int k = 0; k < 4; ++k) acc[i][j][k] = 0.f;

    const uint32_t a_off = (uint32_t)((wm * 32 + (lane & 15)) * ASTR + ((lane >> 4) * 16));
    const uint32_t b_off = (uint32_t)((wn * 64 + (lane & 7) + ((lane & 16) >> 1)) * ASTR
                                      + (((lane >> 3) & 1) * 16));

    const int ar = tid >> 2, asg = tid & 3;        // A: row, 8-float segment
    const int bc = tid >> 1, bsg = tid & 1;        // B: col, 16-float segment

    #define STAGE(k0, bufp) do {                                                   \
        {                                                                          \
            const float4* s = reinterpret_cast<const float4*>(                     \
                xg + (size_t)ar * DIMK + (k0) + asg * 8);                           \
            float4 f0 = s[0], f1 = s[1];                                           \
            *reinterpret_cast<uint4*>((bufp) + OFF_AH + ar * ASTR + asg * 16) =     \
                make_uint4(cvt2(f0.x, f0.y), cvt2(f0.z, f0.w),                      \
                           cvt2(f1.x, f1.y), cvt2(f1.z, f1.w));                     \
        }                                                                          \
        {                                                                          \
            const float4* s = reinterpret_cast<const float4*>(                     \
                Wg + (size_t)bc * DIMK + (k0) + bsg * 16);                          \
            float4 f0 = s[0], f1 = s[1], f2 = s[2], f3 = s[3];                      \
            char* bp = (bufp) + OFF_BH + bc * ASTR + bsg * 32;                      \
            *reinterpret_cast<uint4*>(bp) =                                         \
                make_uint4(cvt2(f0.x, f0.y), cvt2(f0.z, f0.w),                      \
                           cvt2(f1.x, f1.y), cvt2(f1.z, f1.w));                     \
            *reinterpret_cast<uint4*>(bp + 16) =                                    \
                make_uint4(cvt2(f2.x, f2.y), cvt2(f2.z, f2.w),                      \
                           cvt2(f3.x, f3.y), cvt2(f3.z, f3.w));                     \
        }                                                                          \
    } while (0)

    STAGE(0, smem + SM_BUF);
    __syncthreads();

    #pragma unroll 1
    for (int c = 0; c < NCHUNK; ++c) {
        if (c + 1 < NCHUNK)
            STAGE((c + 1) * KC, smem + SM_BUF + ((c + 1) & 1) * BUFSZ);

        const uint32_t bbase = sb + SM_BUF + (c & 1) * BUFSZ;
        #pragma unroll
        for (int ks = 0; ks < 2; ++ks) {
            uint32_t ah[2][4];
            #pragma unroll
            for (int mi = 0; mi < 2; ++mi)
                ldm4(ah[mi], bbase + OFF_AH + a_off + mi * (16 * ASTR) + ks * 32);
            #pragma unroll
            for (int nh = 0; nh < 2; ++nh) {
                uint32_t bh[2][4];
                #pragma unroll
                for (int ng = 0; ng < 2; ++ng)
                    ldm4(bh[ng], bbase + OFF_BH + b_off
                         + (uint32_t)((nh * 32 + ng * 16) * ASTR) + ks * 32);
                #pragma unroll
                for (int mi = 0; mi < 2; ++mi) {
                    #pragma unroll
                    for (int nt = 0; nt < 4; ++nt) {
                        const int ng = nt >> 1, rr = (nt & 1) * 2;
                        mma_bf16(acc[mi][nh * 4 + nt], ah[mi],
                                 bh[ng][rr], bh[ng][rr + 1]);
                    }
                }
            }
        }
        __syncthreads();
    }
    #undef STAGE

    // ---- epilogue: bias + per-warp top-2 over warp's 64 cols ----
    const float* sbias = reinterpret_cast<const float*>(smem + SM_BIAS);
    float* sV1 = reinterpret_cast<float*>(smem + SM_V1);
    float* sV2 = reinterpret_cast<float*>(smem + SM_V2);
    int*   sI1 = reinterpret_cast<int*>(smem + SM_I1);

    const int g = lane >> 2, q = lane & 3;
    const int colbase = wn * 64;

    #pragma unroll
    for (int mi = 0; mi < 2; ++mi) {
        #pragma unroll
        for (int h8 = 0; h8 < 2; ++h8) {
            const int row_local = wm * 32 + mi * 16 + h8 * 8 + g;
            float bv = -3.402823466e38f, bv2 = -3.402823466e38f;
            int bc_ = 0;
            #pragma unroll
            for (int nt = 0; nt < 8; ++nt) {
                const int c0 = colbase + nt * 8 + 2 * q;
                float v0 = acc[mi][nt][h8 * 2 + 0] + sbias[c0];
                float v1 = acc[mi][nt][h8 * 2 + 1] + sbias[c0 + 1];
                if (v0 > bv) { bv2 = bv; bv = v0; bc_ = c0; }
                else if (v0 > bv2) bv2 = v0;
                if (v1 > bv) { bv2 = bv; bv = v1; bc_ = c0 + 1; }
                else if (v1 > bv2) bv2 = v1;
            }
            #pragma unroll
            for (int off = 1; off <= 2; off <<= 1) {
                float ov  = __shfl_xor_sync(0xffffffffu, bv,  off);
                float ov2 = __shfl_xor_sync(0xffffffffu, bv2, off);
                int   oc  = __shfl_xor_sync(0xffffffffu, bc_, off);
                if (ov > bv || (ov == bv && oc < bc_)) {
                    bv2 = fmaxf(bv, ov2); bv = ov; bc_ = oc;
                } else {
                    bv2 = fmaxf(bv2, ov);
                }
            }
            if (q == 0) {
                sV1[row_local * 4 + wn] = bv;
                sV2[row_local * 4 + wn] = bv2;
                sI1[row_local * 4 + wn] = bc_;
            }
        }
    }
    __syncthreads();

    if (tid < TM) {
        float bv = sV1[tid * 4], bv2 = sV2[tid * 4];
        int bc_ = sI1[tid * 4];
        #pragma unroll
        for (int w = 1; w < 4; ++w) {
            float ov = sV1[tid * 4 + w], ov2 = sV2[tid * 4 + w];
            int oc = sI1[tid * 4 + w];
            if (ov > bv) { bv2 = fmaxf(bv, ov2); bv = ov; bc_ = oc; }
            else bv2 = fmaxf(bv2, ov);
        }
        const int grow = row0 + tid;
        gidx[grow * NCB + cb] = bc_;
        if (bv - bv2 < GAP_TAU) {
            int pos = atomicAdd(&g_cnt_cb[cb], 1);
            g_list_cb[cb * CAP_CB + pos] = grow;   // pos < 32768 by construction
        }
    }
}

// ---------------------------------------------------------------------------
__global__ void init_kernel() {
    if (threadIdx.x < NCB) g_cnt_cb[threadIdx.x] = 0;
}

// ---------------------------------------------------------------------------
// Kernel 2: exact fp32 recheck, coalesced + cb-batched (8 rows per pass).
// grid = (512, NCB), block = 256 (thread = column).
// Per (row, col): single sequential fma chain over k = 0..511 — bitwise the
// round-1 order that matched the reference argmax on every pair.
// ---------------------------------------------------------------------------
#define RB 512
__global__ __launch_bounds__(256)
void recheck_kernel(const float* __restrict__ x,
                    const float* __restrict__ W,
                    const float* __restrict__ bias,
                    int* __restrict__ gidx)
{
    __shared__ float Wsm[CS * 33];   // [col][k], stride 33 (conflict-free)
    __shared__ float xs[8 * 32];
    __shared__ int   rl[8];
    __shared__ float rv[8];
    __shared__ int   rc[8];

    const int cb  = blockIdx.y;
    const int tid = threadIdx.x;
    const int n   = g_cnt_cb[cb];
    const float bcol = bias[cb * CS + tid];
    const float* Wcb = W + (size_t)cb * CS * DIMK;

    for (int base = blockIdx.x * 8; base < n; base += RB * 8) {
        const int m = min(8, n - base);
        __syncthreads();   // protect rl/xs/Wsm from previous pass
        if (tid < 8)
            rl[tid] = (tid < m) ? g_list_cb[cb * CAP_CB + base + tid] : 0;
        __syncthreads();

        float acc[8];
        #pragma unroll
        for (int r = 0; r < 8; ++r) acc[r] = 0.f;

        const int xr_ = tid >> 5, xk = tid & 31;     // x staging
        const int wrow = tid >> 3, wseg = tid & 7;   // W staging (8 thr/row)

        #pragma unroll 1
        for (int c = 0; c < NCHUNK; ++c) {
            const int k0 = c * KC;
            __syncthreads();
            // stage x: 8 rows x 32 k
            xs[tid & 255] = (xr_ < m)
                ? x[(size_t)rl[xr_] * DIMK + k0 + xk] : 0.f;
            // stage W chunk: 256 cols x 32 k, coalesced float4 loads
            #pragma unroll
            for (int e = 0; e < 8; ++e) {
                const int f = tid + 256 * e;
                const int row = f >> 3, seg = f & 7;
                float4 v = *reinterpret_cast<const float4*>(
                    Wcb + (size_t)row * DIMK + k0 + seg * 4);
                float* d = &Wsm[row * 33 + seg * 4];
                d[0] = v.x; d[1] = v.y; d[2] = v.z; d[3] = v.w;
            }
            __syncthreads();
            // compute: k ascending, one sequential chain per (row, col)
            #pragma unroll
            for (int k = 0; k < KC; ++k) {
                const float wv = Wsm[tid * 33 + k];
                #pragma unroll
                for (int r = 0; r < 8; ++r)
                    acc[r] = fmaf(xs[r * 32 + k], wv, acc[r]);
            }
        }

        // argmax per row (256 cols), tie -> smaller index
        #pragma unroll 1
        for (int r = 0; r < 8; ++r) {
            if (r >= m) break;
            float v = acc[r] + bcol;
            int cidx = tid;
            #pragma unroll
            for (int off = 16; off; off >>= 1) {
                float ov = __shfl_xor_sync(0xffffffffu, v, off);
                int   oc = __shfl_xor_sync(0xffffffffu, cidx, off);
                if (ov > v || (ov == v && oc < cidx)) { v = ov; cidx = oc; }
            }
            if ((tid & 31) == 0) { rv[tid >> 5] = v; rc[tid >> 5] = cidx; }
            __syncthreads();
            if (tid == 0) {
                #pragma unroll
                for (int w = 1; w < 8; ++w)
                    if (rv[w] > v || (rv[w] == v && rc[w] < cidx)) {
                        v = rv[w]; cidx = rc[w];
                    }
                gidx[rl[r] * NCB + cb] = cidx;
            }
            __syncthreads();
        }
    }
}

// ---------------------------------------------------------------------------
// Kernel 3: decode — gather 16 centers per row, sum, scale.
// ---------------------------------------------------------------------------
__global__ __launch_bounds__(128)
void dec_gather_kernel(const float* __restrict__ centers,
                       const int* __restrict__ gidx,
                       const float* __restrict__ centers_scale,
                       float* __restrict__ out)
{
    __shared__ int   sidx[NCB];
    __shared__ float sscale;
    const int row = blockIdx.x;
    const int tid = threadIdx.x;

    if (tid < NCB) sidx[tid] = gidx[row * NCB + tid];
    if (tid == 0)  sscale = expf(10.0f * centers_scale[0]);
    __syncthreads();

    float4 s = make_float4(0.f, 0.f, 0.f, 0.f);
    #pragma unroll
    for (int c = 0; c < NCB; ++c) {
        const float4* p = reinterpret_cast<const float4*>(
            centers + ((size_t)((c << 8) + sidx[c])) * DIMK);
        float4 v = __ldg(&p[tid]);
        s.x += v.x; s.y += v.y; s.z += v.z; s.w += v.w;
    }
    float sc = sscale;
    s.x *= sc; s.y *= sc; s.z *= sc; s.w *= sc;
    reinterpret_cast<float4*>(out)[(size_t)row * (DIMK / 4) + tid] = s;
}

// ---------------------------------------------------------------------------
extern "C" void kernel_launch(void* const* d_in, const int* in_sizes, int n_in,
                              void* d_out, int out_size)
{
    const float* x       = (const float*)d_in[0];
    const float* W       = (const float*)d_in[1];
    const float* b       = (const float*)d_in[2];
    const float* centers = (const float*)d_in[3];
    const float* cscale  = (const float*)d_in[5];
    float* out           = (float*)d_out;

    int* gidx_ptr = nullptr;
    cudaGetSymbolAddress((void**)&gidx_ptr, g_idx);

    cudaFuncSetAttribute(enc_mma_kernel,
                         cudaFuncAttributeMaxDynamicSharedMemorySize, SMEM_TOTAL);

    init_kernel<<<1, 32>>>();
    dim3 grid1(NCB, NROWS / TM);
    enc_mma_kernel<<<grid1, TPB, SMEM_TOTAL>>>(x, W, b, gidx_ptr);
    dim3 grid2(RB, NCB);
    recheck_kernel<<<grid2, 256>>>(x, W, b, gidx_ptr);
    dec_gather_kernel<<<NROWS, 128>>>(centers, gidx_ptr, cscale, out);
}

// round 8
// speedup vs baseline: 24.3246x; 1.8111x over previous
#include <cuda_runtime.h>
#include <cuda_bf16.h>
#include <cstdint>

// Problem constants
#define NROWS 32768
#define DIMK  512
#define NCB   16
#define CS    256

// Encoder tiling
#define TM    128
#define TN    256
#define KC    64
#define NCHUNK (DIMK / KC)   // 8
#define TPB   512
#define NSTAGE 3

#define GAP_TAU 0.015f
#define CAP_CB  32768

__device__ int g_idx[NROWS * NCB];
__device__ int g_cnt_cb[NCB];
__device__ int g_list_cb[NCB * CAP_CB];
__device__ __nv_bfloat16 g_xbf[NROWS * DIMK];     // 32 MB
__device__ __nv_bfloat16 g_wbf[NCB * CS * DIMK];  // 4 MB

// ---------------- enc smem layout (dynamic) ----------------
#define SM_BIAS 0          // 1024B
#define SM_V1   1024       // 2048B
#define SM_V2   3072       // 2048B
#define SM_I1   5120       // 2048B
#define SM_BUF  7168
#define ASTR    144        // 64 bf16 = 128B + 16B pad (9 granules, odd -> conflict-free)
#define OFF_A   0
#define OFF_B   18432      // 128*144
#define BUFSZ   55296      // + 256*144
#define SMEM_TOTAL (SM_BUF + NSTAGE * BUFSZ)   // 173056 B

__device__ __forceinline__ uint32_t smem_u32(const void* p) {
    uint32_t a;
    asm("{ .reg .u64 t; cvta.to.shared.u64 t, %1; cvt.u32.u64 %0, t; }"
        : "=r"(a) : "l"(p));
    return a;
}
__device__ __forceinline__ void ldm4(uint32_t r[4], uint32_t addr) {
    asm volatile("ldmatrix.sync.aligned.m8n8.x4.shared.b16 {%0,%1,%2,%3}, [%4];"
        : "=r"(r[0]), "=r"(r[1]), "=r"(r[2]), "=r"(r[3]) : "r"(addr));
}
__device__ __forceinline__ void mma_bf16(float d[4], const uint32_t a[4],
                                         uint32_t b0, uint32_t b1) {
    asm volatile("mma.sync.aligned.m16n8k16.row.col.f32.bf16.bf16.f32 "
        "{%0,%1,%2,%3},{%4,%5,%6,%7},{%8,%9},{%0,%1,%2,%3};"
        : "+f"(d[0]), "+f"(d[1]), "+f"(d[2]), "+f"(d[3])
        : "r"(a[0]), "r"(a[1]), "r"(a[2]), "r"(a[3]), "r"(b0), "r"(b1));
}
__device__ __forceinline__ uint32_t cvt2(float a, float b) {
    uint32_t r;
    asm("cvt.rn.bf16x2.f32 %0, %1, %2;" : "=r"(r) : "f"(b), "f"(a));
    return r;
}
__device__ __forceinline__ void cpa16(uint32_t dst, const void* src) {
    asm volatile("cp.async.cg.shared.global [%0], [%1], 16;"
                 :: "r"(dst), "l"(src));
}

// ---------------------------------------------------------------------------
// Kernel 0: fp32 -> bf16 conversion (8 elems / thread)
// ---------------------------------------------------------------------------
__global__ __launch_bounds__(256)
void cvt_kernel(const float* __restrict__ src, __nv_bfloat16* __restrict__ dst,
                int n8)
{
    int i = blockIdx.x * blockDim.x + threadIdx.x;
    if (i < n8) {
        const float4* s = reinterpret_cast<const float4*>(src) + (size_t)i * 2;
        float4 a = s[0], b = s[1];
        reinterpret_cast<uint4*>(dst)[i] =
            make_uint4(cvt2(a.x, a.y), cvt2(a.z, a.w),
                       cvt2(b.x, b.y), cvt2(b.z, b.w));
    }
}

// ---------------------------------------------------------------------------
// Kernel 1: pure-bf16 GEMM (mma.sync, cp.async 3-stage) + argmax + tie list.
// grid = (NCB, NROWS/TM), block = 512 (16 warps, 4m x 4n, warp tile 32x64).
// ---------------------------------------------------------------------------
__global__ __launch_bounds__(TPB, 1)
void enc_mma_kernel(const float* __restrict__ bias, int* __restrict__ gidx)
{
    extern __shared__ char smem[];
    const uint32_t sb = smem_u32(smem);
    const int tid  = threadIdx.x;
    const int lane = tid & 31;
    const int wid  = tid >> 5;
    const int wm   = wid >> 2;
    const int wn   = wid & 3;
    const int cb   = blockIdx.x;
    const int row0 = blockIdx.y * TM;

    if (tid < CS)
        *reinterpret_cast<float*>(smem + SM_BIAS + tid * 4) = bias[cb * CS + tid];

    const __nv_bfloat16* xbf = g_xbf + (size_t)row0 * DIMK;
    const __nv_bfloat16* wbf = g_wbf + (size_t)cb * CS * DIMK;

    float acc[2][8][4];
    #pragma unroll
    for (int i = 0; i < 2; ++i)
        #pragma unroll
        for (int j = 0; j < 8; ++j)
            #pragma unroll
            for (int k = 0; k < 4; ++k) acc[i][j][k] = 0.f;

    // cp.async per-thread offsets
    const int seg = tid & 7;                 // 16B segment (8 bf16)
    uint32_t a_dst[2];  size_t a_src[2];
    uint32_t b_dst[4];  size_t b_src[4];
    #pragma unroll
    for (int e = 0; e < 2; ++e) {
        int row = (tid + 512 * e) >> 3;      // 0..127
        a_dst[e] = OFF_A + row * ASTR + seg * 16;
        a_src[e] = (size_t)row * DIMK + seg * 8;
    }
    #pragma unroll
    for (int e = 0; e < 4; ++e) {
        int row = (tid + 512 * e) >> 3;      // 0..255
        b_dst[e] = OFF_B + row * ASTR + seg * 16;
        b_src[e] = (size_t)row * DIMK + seg * 8;
    }

    #define ISSUE(k0, bufu) do {                                   \
        _Pragma("unroll")                                          \
        for (int e = 0; e < 2; ++e)                                \
            cpa16((bufu) + a_dst[e], xbf + a_src[e] + (k0));       \
        _Pragma("unroll")                                          \
        for (int e = 0; e < 4; ++e)                                \
            cpa16((bufu) + b_dst[e], wbf + b_src[e] + (k0));       \
        asm volatile("cp.async.commit_group;" ::: "memory");       \
    } while (0)

    // ldmatrix lane offsets
    const uint32_t a_off = (uint32_t)((wm * 32 + (lane & 15)) * ASTR + ((lane >> 4) * 16));
    const uint32_t b_off = (uint32_t)((wn * 64 + (lane & 7) + ((lane & 16) >> 1)) * ASTR
                                      + (((lane >> 3) & 1) * 16));

    // prologue: stage chunks 0, 1
    ISSUE(0, sb + SM_BUF + 0 * BUFSZ);
    ISSUE(KC, sb + SM_BUF + 1 * BUFSZ);

    int cbuf = 0, ibuf = 2;
    #pragma unroll 1
    for (int c = 0; c < NCHUNK; ++c) {
        if (c + 1 < NCHUNK)
            asm volatile("cp.async.wait_group 1;" ::: "memory");
        else
            asm volatile("cp.async.wait_group 0;" ::: "memory");
        __syncthreads();

        const uint32_t bbase = sb + SM_BUF + cbuf * BUFSZ;
        #pragma unroll
        for (int ks = 0; ks < 4; ++ks) {
            uint32_t ah[2][4];
            #pragma unroll
            for (int mi = 0; mi < 2; ++mi)
                ldm4(ah[mi], bbase + OFF_A + a_off + mi * (16 * ASTR) + ks * 32);
            #pragma unroll
            for (int nh = 0; nh < 2; ++nh) {
                uint32_t bh[2][4];
                #pragma unroll
                for (int ng = 0; ng < 2; ++ng)
                    ldm4(bh[ng], bbase + OFF_B + b_off
                         + (uint32_t)((nh * 32 + ng * 16) * ASTR) + ks * 32);
                #pragma unroll
                for (int mi = 0; mi < 2; ++mi) {
                    #pragma unroll
                    for (int nt = 0; nt < 4; ++nt) {
                        const int ng = nt >> 1, rr = (nt & 1) * 2;
                        mma_bf16(acc[mi][nh * 4 + nt], ah[mi],
                                 bh[ng][rr], bh[ng][rr + 1]);
                    }
                }
            }
        }

        if (c + 2 < NCHUNK) {
            ISSUE((c + 2) * KC, sb + SM_BUF + ibuf * BUFSZ);
            ibuf = (ibuf == NSTAGE - 1) ? 0 : ibuf + 1;
        }
        cbuf = (cbuf == NSTAGE - 1) ? 0 : cbuf + 1;
    }
    #undef ISSUE

    // ---- epilogue: bias + per-warp top-2 over warp's 64 cols ----
    const float* sbias = reinterpret_cast<const float*>(smem + SM_BIAS);
    float* sV1 = reinterpret_cast<float*>(smem + SM_V1);
    float* sV2 = reinterpret_cast<float*>(smem + SM_V2);
    int*   sI1 = reinterpret_cast<int*>(smem + SM_I1);

    const int g = lane >> 2, q = lane & 3;
    const int colbase = wn * 64;

    #pragma unroll
    for (int mi = 0; mi < 2; ++mi) {
        #pragma unroll
        for (int h8 = 0; h8 < 2; ++h8) {
            const int row_local = wm * 32 + mi * 16 + h8 * 8 + g;
            float bv = -3.402823466e38f, bv2 = -3.402823466e38f;
            int bc_ = 0;
            #pragma unroll
            for (int nt = 0; nt < 8; ++nt) {
                const int c0 = colbase + nt * 8 + 2 * q;
                float v0 = acc[mi][nt][h8 * 2 + 0] + sbias[c0];
                float v1 = acc[mi][nt][h8 * 2 + 1] + sbias[c0 + 1];
                if (v0 > bv) { bv2 = bv; bv = v0; bc_ = c0; }
                else if (v0 > bv2) bv2 = v0;
                if (v1 > bv) { bv2 = bv; bv = v1; bc_ = c0 + 1; }
                else if (v1 > bv2) bv2 = v1;
            }
            #pragma unroll
            for (int off = 1; off <= 2; off <<= 1) {
                float ov  = __shfl_xor_sync(0xffffffffu, bv,  off);
                float ov2 = __shfl_xor_sync(0xffffffffu, bv2, off);
                int   oc  = __shfl_xor_sync(0xffffffffu, bc_, off);
                if (ov > bv || (ov == bv && oc < bc_)) {
                    bv2 = fmaxf(bv, ov2); bv = ov; bc_ = oc;
                } else {
                    bv2 = fmaxf(bv2, ov);
                }
            }
            if (q == 0) {
                sV1[row_local * 4 + wn] = bv;
                sV2[row_local * 4 + wn] = bv2;
                sI1[row_local * 4 + wn] = bc_;
            }
        }
    }
    __syncthreads();

    if (tid < TM) {
        float bv = sV1[tid * 4], bv2 = sV2[tid * 4];
        int bc_ = sI1[tid * 4];
        #pragma unroll
        for (int w = 1; w < 4; ++w) {
            float ov = sV1[tid * 4 + w], ov2 = sV2[tid * 4 + w];
            int oc = sI1[tid * 4 + w];
            if (ov > bv) { bv2 = fmaxf(bv, ov2); bv = ov; bc_ = oc; }
            else bv2 = fmaxf(bv2, ov);
        }
        const int grow = row0 + tid;
        gidx[grow * NCB + cb] = bc_;
        if (bv - bv2 < GAP_TAU) {
            int pos = atomicAdd(&g_cnt_cb[cb], 1);
            g_list_cb[cb * CAP_CB + pos] = grow;
        }
    }
}

// ---------------------------------------------------------------------------
__global__ void init_kernel() {
    if (threadIdx.x < NCB) g_cnt_cb[threadIdx.x] = 0;
}

// ---------------------------------------------------------------------------
// Kernel 2: exact fp32 recheck, coalesced + cb-batched (16 rows per pass).
// Single ascending-k fma chain per (row, col) — bitwise the reference-matching
// order. grid = (RB, NCB), block = 256 (thread = column).
// ---------------------------------------------------------------------------
#define RB   256
#define RROWS 16
#define RKC  32
__global__ __launch_bounds__(256)
void recheck_kernel(const float* __restrict__ x,
                    const float* __restrict__ W,
                    const float* __restrict__ bias,
                    int* __restrict__ gidx)
{
    __shared__ float Wsm[CS * 33];
    __shared__ float xs[RROWS * RKC];
    __shared__ int   rl[RROWS];
    __shared__ float rv[8];
    __shared__ int   rc[8];

    const int cb  = blockIdx.y;
    const int tid = threadIdx.x;
    const int n   = g_cnt_cb[cb];
    const float bcol = bias[cb * CS + tid];
    const float* Wcb = W + (size_t)cb * CS * DIMK;

    for (int base = blockIdx.x * RROWS; base < n; base += RB * RROWS) {
        const int m = min(RROWS, n - base);
        __syncthreads();
        if (tid < RROWS)
            rl[tid] = g_list_cb[cb * CAP_CB + base + ((tid < m) ? tid : 0)];
        __syncthreads();

        float acc[RROWS];
        #pragma unroll
        for (int r = 0; r < RROWS; ++r) acc[r] = 0.f;

        #pragma unroll 1
        for (int c = 0; c < DIMK / RKC; ++c) {
            const int k0 = c * RKC;
            __syncthreads();
            // stage x: 16 rows x 32 k (coalesced per row)
            #pragma unroll
            for (int e = 0; e < 2; ++e) {
                const int f = tid + 256 * e;
                xs[f] = x[(size_t)rl[f >> 5] * DIMK + k0 + (f & 31)];
            }
            // stage W chunk: 256 cols x 32 k, coalesced float4
            #pragma unroll
            for (int e = 0; e < 8; ++e) {
                const int f = tid + 256 * e;
                const int row = f >> 3, sg = f & 7;
                float4 v = *reinterpret_cast<const float4*>(
                    Wcb + (size_t)row * DIMK + k0 + sg * 4);
                float* d = &Wsm[row * 33 + sg * 4];
                d[0] = v.x; d[1] = v.y; d[2] = v.z; d[3] = v.w;
            }
            __syncthreads();
            #pragma unroll
            for (int k = 0; k < RKC; ++k) {
                const float wv = Wsm[tid * 33 + k];
                #pragma unroll
                for (int r = 0; r < RROWS; ++r)
                    acc[r] = fmaf(xs[r * RKC + k], wv, acc[r]);
            }
        }

        #pragma unroll 1
        for (int r = 0; r < RROWS; ++r) {
            if (r >= m) break;
            float v = acc[r] + bcol;
            int cidx = tid;
            #pragma unroll
            for (int off = 16; off; off >>= 1) {
                float ov = __shfl_xor_sync(0xffffffffu, v, off);
                int   oc = __shfl_xor_sync(0xffffffffu, cidx, off);
                if (ov > v || (ov == v && oc < cidx)) { v = ov; cidx = oc; }
            }
            if ((tid & 31) == 0) { rv[tid >> 5] = v; rc[tid >> 5] = cidx; }
            __syncthreads();
            if (tid == 0) {
                #pragma unroll
                for (int w = 1; w < 8; ++w)
                    if (rv[w] > v || (rv[w] == v && rc[w] < cidx)) {
                        v = rv[w]; cidx = rc[w];
                    }
                gidx[rl[r] * NCB + cb] = cidx;
            }
            __syncthreads();
        }
    }
}

// ---------------------------------------------------------------------------
// Kernel 3: decode — gather 16 centers per row, sum, scale.
// ---------------------------------------------------------------------------
__global__ __launch_bounds__(128)
void dec_gather_kernel(const float* __restrict__ centers,
                       const int* __restrict__ gidx,
                       const float* __restrict__ centers_scale,
                       float* __restrict__ out)
{
    __shared__ int   sidx[NCB];
    __shared__ float sscale;
    const int row = blockIdx.x;
    const int tid = threadIdx.x;

    if (tid < NCB) sidx[tid] = gidx[row * NCB + tid];
    if (tid == 0)  sscale = expf(10.0f * centers_scale[0]);
    __syncthreads();

    float4 s = make_float4(0.f, 0.f, 0.f, 0.f);
    #pragma unroll
    for (int c = 0; c < NCB; ++c) {
        const float4* p = reinterpret_cast<const float4*>(
            centers + ((size_t)((c << 8) + sidx[c])) * DIMK);
        float4 v = __ldg(&p[tid]);
        s.x += v.x; s.y += v.y; s.z += v.z; s.w += v.w;
    }
    float sc = sscale;
    s.x *= sc; s.y *= sc; s.z *= sc; s.w *= sc;
    reinterpret_cast<float4*>(out)[(size_t)row * (DIMK / 4) + tid] = s;
}

// ---------------------------------------------------------------------------
extern "C" void kernel_launch(void* const* d_in, const int* in_sizes, int n_in,
                              void* d_out, int out_size)
{
    const float* x       = (const float*)d_in[0];
    const float* W       = (const float*)d_in[1];
    const float* b       = (const float*)d_in[2];
    const float* centers = (const float*)d_in[3];
    const float* cscale  = (const float*)d_in[5];
    float* out           = (float*)d_out;

    int* gidx_ptr = nullptr;
    cudaGetSymbolAddress((void**)&gidx_ptr, g_idx);
    __nv_bfloat16* xbf_ptr = nullptr;
    cudaGetSymbolAddress((void**)&xbf_ptr, g_xbf);
    __nv_bfloat16* wbf_ptr = nullptr;
    cudaGetSymbolAddress((void**)&wbf_ptr, g_wbf);

    cudaFuncSetAttribute(enc_mma_kernel,
                         cudaFuncAttributeMaxDynamicSharedMemorySize, SMEM_TOTAL);

    cvt_kernel<<<(NROWS * DIMK / 8 + 255) / 256, 256>>>(x, xbf_ptr, NROWS * DIMK / 8);
    cvt_kernel<<<(NCB * CS * DIMK / 8 + 255) / 256, 256>>>(W, wbf_ptr, NCB * CS * DIMK / 8);
    init_kernel<<<1, 32>>>();
    dim3 grid1(NCB, NROWS / TM);
    enc_mma_kernel<<<grid1, TPB, SMEM_TOTAL>>>(b, gidx_ptr);
    dim3 grid2(RB, NCB);
    recheck_kernel<<<grid2, 256>>>(x, W, b, gidx_ptr);
    dec_gather_kernel<<<NROWS, 128>>>(centers, gidx_ptr, cscale, out);
}

// round 9
// speedup vs baseline: 24.4365x; 1.0046x over previous
#include <cuda_runtime.h>
#include <cuda_bf16.h>
#include <cstdint>

// Problem constants
#define NROWS 32768
#define DIMK  512
#define NCB   16
#define CS    256

// Encoder tiling
#define TM    128
#define TN    256
#define KC    64
#define NCHUNK (DIMK / KC)   // 8
#define TPB   512
#define NSTAGE 3

#define GAP_TAU 0.015f
#define CAP_CB  32768

__device__ int g_idx[NROWS * NCB];
__device__ int g_cnt_cb[NCB];
__device__ int g_list_cb[NCB * CAP_CB];
__device__ __nv_bfloat16 g_xbf[NROWS * DIMK];     // 32 MB
__device__ __nv_bfloat16 g_wbf[NCB * CS * DIMK];  // 4 MB

// ---------------- enc smem layout (dynamic) ----------------
#define SM_BIAS 0          // 1024B
#define SM_V1   1024       // 2048B
#define SM_V2   3072       // 2048B
#define SM_I1   5120       // 2048B
#define SM_BUF  7168
#define ASTR    144        // 64 bf16 = 128B + 16B pad (9 granules, odd -> conflict-free)
#define OFF_A   0
#define OFF_B   18432      // 128*144
#define BUFSZ   55296      // + 256*144
#define SMEM_TOTAL (SM_BUF + NSTAGE * BUFSZ)   // 173056 B

__device__ __forceinline__ uint32_t smem_u32(const void* p) {
    uint32_t a;
    asm("{ .reg .u64 t; cvta.to.shared.u64 t, %1; cvt.u32.u64 %0, t; }"
        : "=r"(a) : "l"(p));
    return a;
}
__device__ __forceinline__ void ldm4(uint32_t r[4], uint32_t addr) {
    asm volatile("ldmatrix.sync.aligned.m8n8.x4.shared.b16 {%0,%1,%2,%3}, [%4];"
        : "=r"(r[0]), "=r"(r[1]), "=r"(r[2]), "=r"(r[3]) : "r"(addr));
}
__device__ __forceinline__ void mma_bf16(float d[4], const uint32_t a[4],
                                         uint32_t b0, uint32_t b1) {
    asm volatile("mma.sync.aligned.m16n8k16.row.col.f32.bf16.bf16.f32 "
        "{%0,%1,%2,%3},{%4,%5,%6,%7},{%8,%9},{%0,%1,%2,%3};"
        : "+f"(d[0]), "+f"(d[1]), "+f"(d[2]), "+f"(d[3])
        : "r"(a[0]), "r"(a[1]), "r"(a[2]), "r"(a[3]), "r"(b0), "r"(b1));
}
__device__ __forceinline__ uint32_t cvt2(float a, float b) {
    uint32_t r;
    asm("cvt.rn.bf16x2.f32 %0, %1, %2;" : "=r"(r) : "f"(b), "f"(a));
    return r;
}
__device__ __forceinline__ void cpa16(uint32_t dst, const void* src) {
    asm volatile("cp.async.cg.shared.global [%0], [%1], 16;"
                 :: "r"(dst), "l"(src));
}

// ---------------------------------------------------------------------------
// Kernel 0: fp32 -> bf16 conversion (8 elems / thread)
// ---------------------------------------------------------------------------
__global__ __launch_bounds__(256)
void cvt_kernel(const float* __restrict__ src, __nv_bfloat16* __restrict__ dst,
                int n8)
{
    int i = blockIdx.x * blockDim.x + threadIdx.x;
    if (i < n8) {
        const float4* s = reinterpret_cast<const float4*>(src) + (size_t)i * 2;
        float4 a = s[0], b = s[1];
        reinterpret_cast<uint4*>(dst)[i] =
            make_uint4(cvt2(a.x, a.y), cvt2(a.z, a.w),
                       cvt2(b.x, b.y), cvt2(b.z, b.w));
    }
}

// ---------------------------------------------------------------------------
// Kernel 1: pure-bf16 GEMM (mma.sync, cp.async 3-stage) + argmax + tie list.
// grid = (NCB, NROWS/TM), block = 512 (16 warps, 4m x 4n, warp tile 32x64).
// ---------------------------------------------------------------------------
__global__ __launch_bounds__(TPB, 1)
void enc_mma_kernel(const float* __restrict__ bias, int* __restrict__ gidx)
{
    extern __shared__ char smem[];
    const uint32_t sb = smem_u32(smem);
    const int tid  = threadIdx.x;
    const int lane = tid & 31;
    const int wid  = tid >> 5;
    const int wm   = wid >> 2;
    const int wn   = wid & 3;
    const int cb   = blockIdx.x;
    const int row0 = blockIdx.y * TM;

    if (tid < CS)
        *reinterpret_cast<float*>(smem + SM_BIAS + tid * 4) = bias[cb * CS + tid];

    const __nv_bfloat16* xbf = g_xbf + (size_t)row0 * DIMK;
    const __nv_bfloat16* wbf = g_wbf + (size_t)cb * CS * DIMK;

    float acc[2][8][4];
    #pragma unroll
    for (int i = 0; i < 2; ++i)
        #pragma unroll
        for (int j = 0; j < 8; ++j)
            #pragma unroll
            for (int k = 0; k < 4; ++k) acc[i][j][k] = 0.f;

    // cp.async per-thread offsets
    const int seg = tid & 7;                 // 16B segment (8 bf16)
    uint32_t a_dst[2];  size_t a_src[2];
    uint32_t b_dst[4];  size_t b_src[4];
    #pragma unroll
    for (int e = 0; e < 2; ++e) {
        int row = (tid + 512 * e) >> 3;      // 0..127
        a_dst[e] = OFF_A + row * ASTR + seg * 16;
        a_src[e] = (size_t)row * DIMK + seg * 8;
    }
    #pragma unroll
    for (int e = 0; e < 4; ++e) {
        int row = (tid + 512 * e) >> 3;      // 0..255
        b_dst[e] = OFF_B + row * ASTR + seg * 16;
        b_src[e] = (size_t)row * DIMK + seg * 8;
    }

    #define ISSUE(k0, bufu) do {                                   \
        _Pragma("unroll")                                          \
        for (int e = 0; e < 2; ++e)                                \
            cpa16((bufu) + a_dst[e], xbf + a_src[e] + (k0));       \
        _Pragma("unroll")                                          \
        for (int e = 0; e < 4; ++e)                                \
            cpa16((bufu) + b_dst[e], wbf + b_src[e] + (k0));       \
        asm volatile("cp.async.commit_group;" ::: "memory");       \
    } while (0)

    // ldmatrix lane offsets
    const uint32_t a_off = (uint32_t)((wm * 32 + (lane & 15)) * ASTR + ((lane >> 4) * 16));
    const uint32_t b_off = (uint32_t)((wn * 64 + (lane & 7) + ((lane & 16) >> 1)) * ASTR
                                      + (((lane >> 3) & 1) * 16));

    // prologue: stage chunks 0, 1
    ISSUE(0, sb + SM_BUF + 0 * BUFSZ);
    ISSUE(KC, sb + SM_BUF + 1 * BUFSZ);

    int cbuf = 0, ibuf = 2;
    #pragma unroll 1
    for (int c = 0; c < NCHUNK; ++c) {
        if (c + 1 < NCHUNK)
            asm volatile("cp.async.wait_group 1;" ::: "memory");
        else
            asm volatile("cp.async.wait_group 0;" ::: "memory");
        __syncthreads();

        const uint32_t bbase = sb + SM_BUF + cbuf * BUFSZ;
        #pragma unroll
        for (int ks = 0; ks < 4; ++ks) {
            uint32_t ah[2][4];
            #pragma unroll
            for (int mi = 0; mi < 2; ++mi)
                ldm4(ah[mi], bbase + OFF_A + a_off + mi * (16 * ASTR) + ks * 32);
            #pragma unroll
            for (int nh = 0; nh < 2; ++nh) {
                uint32_t bh[2][4];
                #pragma unroll
                for (int ng = 0; ng < 2; ++ng)
                    ldm4(bh[ng], bbase + OFF_B + b_off
                         + (uint32_t)((nh * 32 + ng * 16) * ASTR) + ks * 32);
                #pragma unroll
                for (int mi = 0; mi < 2; ++mi) {
                    #pragma unroll
                    for (int nt = 0; nt < 4; ++nt) {
                        const int ng = nt >> 1, rr = (nt & 1) * 2;
                        mma_bf16(acc[mi][nh * 4 + nt], ah[mi],
                                 bh[ng][rr], bh[ng][rr + 1]);
                    }
                }
            }
        }

        if (c + 2 < NCHUNK) {
            ISSUE((c + 2) * KC, sb + SM_BUF + ibuf * BUFSZ);
            ibuf = (ibuf == NSTAGE - 1) ? 0 : ibuf + 1;
        }
        cbuf = (cbuf == NSTAGE - 1) ? 0 : cbuf + 1;
    }
    #undef ISSUE

    // ---- epilogue: bias + per-warp top-2 over warp's 64 cols ----
    const float* sbias = reinterpret_cast<const float*>(smem + SM_BIAS);
    float* sV1 = reinterpret_cast<float*>(smem + SM_V1);
    float* sV2 = reinterpret_cast<float*>(smem + SM_V2);
    int*   sI1 = reinterpret_cast<int*>(smem + SM_I1);

    const int g = lane >> 2, q = lane & 3;
    const int colbase = wn * 64;

    #pragma unroll
    for (int mi = 0; mi < 2; ++mi) {
        #pragma unroll
        for (int h8 = 0; h8 < 2; ++h8) {
            const int row_local = wm * 32 + mi * 16 + h8 * 8 + g;
            float bv = -3.402823466e38f, bv2 = -3.402823466e38f;
            int bc_ = 0;
            #pragma unroll
            for (int nt = 0; nt < 8; ++nt) {
                const int c0 = colbase + nt * 8 + 2 * q;
                float v0 = acc[mi][nt][h8 * 2 + 0] + sbias[c0];
                float v1 = acc[mi][nt][h8 * 2 + 1] + sbias[c0 + 1];
                if (v0 > bv) { bv2 = bv; bv = v0; bc_ = c0; }
                else if (v0 > bv2) bv2 = v0;
                if (v1 > bv) { bv2 = bv; bv = v1; bc_ = c0 + 1; }
                else if (v1 > bv2) bv2 = v1;
            }
            #pragma unroll
            for (int off = 1; off <= 2; off <<= 1) {
                float ov  = __shfl_xor_sync(0xffffffffu, bv,  off);
                float ov2 = __shfl_xor_sync(0xffffffffu, bv2, off);
                int   oc  = __shfl_xor_sync(0xffffffffu, bc_, off);
                if (ov > bv || (ov == bv && oc < bc_)) {
                    bv2 = fmaxf(bv, ov2); bv = ov; bc_ = oc;
                } else {
                    bv2 = fmaxf(bv2, ov);
                }
            }
            if (q == 0) {
                sV1[row_local * 4 + wn] = bv;
                sV2[row_local * 4 + wn] = bv2;
                sI1[row_local * 4 + wn] = bc_;
            }
        }
    }
    __syncthreads();

    if (tid < TM) {
        float bv = sV1[tid * 4], bv2 = sV2[tid * 4];
        int bc_ = sI1[tid * 4];
        #pragma unroll
        for (int w = 1; w < 4; ++w) {
            float ov = sV1[tid * 4 + w], ov2 = sV2[tid * 4 + w];
            int oc = sI1[tid * 4 + w];
            if (ov > bv) { bv2 = fmaxf(bv, ov2); bv = ov; bc_ = oc; }
            else bv2 = fmaxf(bv2, ov);
        }
        const int grow = row0 + tid;
        gidx[grow * NCB + cb] = bc_;
        if (bv - bv2 < GAP_TAU) {
            int pos = atomicAdd(&g_cnt_cb[cb], 1);
            g_list_cb[cb * CAP_CB + pos] = grow;
        }
    }
}

// ---------------------------------------------------------------------------
__global__ void init_kernel() {
    if (threadIdx.x < NCB) g_cnt_cb[threadIdx.x] = 0;
}

// ---------------------------------------------------------------------------
// Kernel 2: exact fp32 recheck, coalesced + cb-batched (16 rows per pass).
// Single ascending-k fma chain per (row, col) — bitwise the reference-matching
// order. grid = (RB, NCB), block = 256 (thread = column).
// ---------------------------------------------------------------------------
#define RB   256
#define RROWS 16
#define RKC  32
__global__ __launch_bounds__(256)
void recheck_kernel(const float* __restrict__ x,
                    const float* __restrict__ W,
                    const float* __restrict__ bias,
                    int* __restrict__ gidx)
{
    __shared__ float Wsm[CS * 33];
    __shared__ float xs[RROWS * RKC];
    __shared__ int   rl[RROWS];
    __shared__ float rv[8];
    __shared__ int   rc[8];

    const int cb  = blockIdx.y;
    const int tid = threadIdx.x;
    const int n   = g_cnt_cb[cb];
    const float bcol = bias[cb * CS + tid];
    const float* Wcb = W + (size_t)cb * CS * DIMK;

    for (int base = blockIdx.x * RROWS; base < n; base += RB * RROWS) {
        const int m = min(RROWS, n - base);
        __syncthreads();
        if (tid < RROWS)
            rl[tid] = g_list_cb[cb * CAP_CB + base + ((tid < m) ? tid : 0)];
        __syncthreads();

        float acc[RROWS];
        #pragma unroll
        for (int r = 0; r < RROWS; ++r) acc[r] = 0.f;

        #pragma unroll 1
        for (int c = 0; c < DIMK / RKC; ++c) {
            const int k0 = c * RKC;
            __syncthreads();
            // stage x: 16 rows x 32 k (coalesced per row)
            #pragma unroll
            for (int e = 0; e < 2; ++e) {
                const int f = tid + 256 * e;
                xs[f] = x[(size_t)rl[f >> 5] * DIMK + k0 + (f & 31)];
            }
            // stage W chunk: 256 cols x 32 k, coalesced float4
            #pragma unroll
            for (int e = 0; e < 8; ++e) {
                const int f = tid + 256 * e;
                const int row = f >> 3, sg = f & 7;
                float4 v = *reinterpret_cast<const float4*>(
                    Wcb + (size_t)row * DIMK + k0 + sg * 4);
                float* d = &Wsm[row * 33 + sg * 4];
                d[0] = v.x; d[1] = v.y; d[2] = v.z; d[3] = v.w;
            }
            __syncthreads();
            #pragma unroll
            for (int k = 0; k < RKC; ++k) {
                const float wv = Wsm[tid * 33 + k];
                #pragma unroll
                for (int r = 0; r < RROWS; ++r)
                    acc[r] = fmaf(xs[r * RKC + k], wv, acc[r]);
            }
        }

        #pragma unroll 1
        for (int r = 0; r < RROWS; ++r) {
            if (r >= m) break;
            float v = acc[r] + bcol;
            int cidx = tid;
            #pragma unroll
            for (int off = 16; off; off >>= 1) {
                float ov = __shfl_xor_sync(0xffffffffu, v, off);
                int   oc = __shfl_xor_sync(0xffffffffu, cidx, off);
                if (ov > v || (ov == v && oc < cidx)) { v = ov; cidx = oc; }
            }
            if ((tid & 31) == 0) { rv[tid >> 5] = v; rc[tid >> 5] = cidx; }
            __syncthreads();
            if (tid == 0) {
                #pragma unroll
                for (int w = 1; w < 8; ++w)
                    if (rv[w] > v || (rv[w] == v && rc[w] < cidx)) {
                        v = rv[w]; cidx = rc[w];
                    }
                gidx[rl[r] * NCB + cb] = cidx;
            }
            __syncthreads();
        }
    }
}

// ---------------------------------------------------------------------------
// Kernel 3: decode — gather 16 centers per row, sum, scale.
// ---------------------------------------------------------------------------
__global__ __launch_bounds__(128)
void dec_gather_kernel(const float* __restrict__ centers,
                       const int* __restrict__ gidx,
                       const float* __restrict__ centers_scale,
                       float* __restrict__ out)
{
    __shared__ int   sidx[NCB];
    __shared__ float sscale;
    const int row = blockIdx.x;
    const int tid = threadIdx.x;

    if (tid < NCB) sidx[tid] = gidx[row * NCB + tid];
    if (tid == 0)  sscale = expf(10.0f * centers_scale[0]);
    __syncthreads();

    float4 s = make_float4(0.f, 0.f, 0.f, 0.f);
    #pragma unroll
    for (int c = 0; c < NCB; ++c) {
        const float4* p = reinterpret_cast<const float4*>(
            centers + ((size_t)((c << 8) + sidx[c])) * DIMK);
        float4 v = __ldg(&p[tid]);
        s.x += v.x; s.y += v.y; s.z += v.z; s.w += v.w;
    }
    float sc = sscale;
    s.x *= sc; s.y *= sc; s.z *= sc; s.w *= sc;
    reinterpret_cast<float4*>(out)[(size_t)row * (DIMK / 4) + tid] = s;
}

// ---------------------------------------------------------------------------
extern "C" void kernel_launch(void* const* d_in, const int* in_sizes, int n_in,
                              void* d_out, int out_size)
{
    const float* x       = (const float*)d_in[0];
    const float* W       = (const float*)d_in[1];
    const float* b       = (const float*)d_in[2];
    const float* centers = (const float*)d_in[3];
    const float* cscale  = (const float*)d_in[5];
    float* out           = (float*)d_out;

    int* gidx_ptr = nullptr;
    cudaGetSymbolAddress((void**)&gidx_ptr, g_idx);
    __nv_bfloat16* xbf_ptr = nullptr;
    cudaGetSymbolAddress((void**)&xbf_ptr, g_xbf);
    __nv_bfloat16* wbf_ptr = nullptr;
    cudaGetSymbolAddress((void**)&wbf_ptr, g_wbf);

    cudaFuncSetAttribute(enc_mma_kernel,
                         cudaFuncAttributeMaxDynamicSharedMemorySize, SMEM_TOTAL);

    cvt_kernel<<<(NROWS * DIMK / 8 + 255) / 256, 256>>>(x, xbf_ptr, NROWS * DIMK / 8);
    cvt_kernel<<<(NCB * CS * DIMK / 8 + 255) / 256, 256>>>(W, wbf_ptr, NCB * CS * DIMK / 8);
    init_kernel<<<1, 32>>>();
    dim3 grid1(NCB, NROWS / TM);
    enc_mma_kernel<<<grid1, TPB, SMEM_TOTAL>>>(b, gidx_ptr);
    dim3 grid2(RB, NCB);
    recheck_kernel<<<grid2, 256>>>(x, W, b, gidx_ptr);
    dec_gather_kernel<<<NROWS, 128>>>(centers, gidx_ptr, cscale, out);
}